// round 15
// baseline (speedup 1.0000x reference)
#include <cuda_runtime.h>
#include <cuda_bf16.h>

#define N_USERS 100000
#define N_ITEMS 50000
#define NN      150000
#define NE      2000000
#define DD      64
#define NB      16384
#define SB      586      // ceil(NN/256) scan blocks

// ---------------- scratch (device globals) ----------------------------------
__device__ __nv_bfloat16  g_xb[NN*DD];    // layer outputs (bf16)
__device__ __nv_bfloat16  g_hb[NN*DD];    // h = x@W in bf16 (gather payload)
__device__ float g_as [NN*4];
__device__ float g_ad [NN*4];
__device__ int   g_adj[NE];
__device__ int   g_cnt[NN];               // zero at entry (re-zeroed in k_s3)
__device__ int   g_off[NN+1];
__device__ int   g_pos[NN];
__device__ int   g_spine[1024];

// ---------------- helpers ---------------------------------------------------
__device__ __forceinline__ float lrelu(float x) { return x > 0.f ? x : 0.2f * x; }
__device__ __forceinline__ float eluf (float v) { return v > 0.f ? v : expf(v) - 1.f; }
__device__ __forceinline__ float2 bf2f(unsigned u) {
    return __bfloat1622float2(*(__nv_bfloat162*)&u);
}
__device__ __forceinline__ unsigned f2bf2(float a, float b) {
    __nv_bfloat162 p = __float22bfloat162_rn(make_float2(a, b));
    return *(unsigned*)&p;
}
__device__ __forceinline__ unsigned smaddr(const void* p) {
    return (unsigned)__cvta_generic_to_shared(p);
}
__device__ __forceinline__ void ldsm_x4(unsigned* r, unsigned a) {
    asm volatile("ldmatrix.sync.aligned.m8n8.x4.shared.b16 {%0,%1,%2,%3}, [%4];"
                 : "=r"(r[0]), "=r"(r[1]), "=r"(r[2]), "=r"(r[3]) : "r"(a));
}
__device__ __forceinline__ void ldsm_x2t(unsigned* r, unsigned a) {
    asm volatile("ldmatrix.sync.aligned.m8n8.x2.trans.shared.b16 {%0,%1}, [%2];"
                 : "=r"(r[0]), "=r"(r[1]) : "r"(a));
}
__device__ __forceinline__ void mma_bf16(float* c, const unsigned* a, const unsigned* b) {
    asm volatile("mma.sync.aligned.m16n8k16.row.col.f32.bf16.bf16.f32 "
                 "{%0,%1,%2,%3}, {%4,%5,%6,%7}, {%8,%9}, {%0,%1,%2,%3};"
                 : "+f"(c[0]), "+f"(c[1]), "+f"(c[2]), "+f"(c[3])
                 : "r"(a[0]), "r"(a[1]), "r"(a[2]), "r"(a[3]),
                   "r"(b[0]), "r"(b[1]));
}

// per-block int64-vs-int32 detection: one warp, 2 loads/lane + ballot.
// (node ids < 150000 << 2^31, so int64 => every odd 32-bit word is zero)
__device__ __forceinline__ int detect_is64_block(const void* ei, int* sflag) {
    int t = threadIdx.x;
    if (t < 32) {
        const int* p = (const int*)ei;
        int v = p[2 * t + 1] | p[2 * (t + 32) + 1];
        unsigned b = __ballot_sync(0xffffffffu, v != 0);
        if (t == 0) *sflag = (b == 0);
    }
    __syncthreads();
    return *sflag;
}

// ---------------- CSR build ----------------------------------------------------
__global__ void k_count(const void* __restrict__ ei) {
    __shared__ int sis64;
    int is64 = detect_is64_block(ei, &sis64);
    int e = blockIdx.x * blockDim.x + threadIdx.x;
    if (e >= NE) return;
    int d = is64 ? (int)((const long long*)ei)[NE + e]
                 : ((const int*)ei)[NE + e];
    atomicAdd(&g_cnt[d], 1);
}

// block sums -> spine (shuffle reduce)
__global__ void k_s1() {
    __shared__ int ws[8];
    int t = threadIdx.x;
    int i = blockIdx.x * 256 + t;
    int v = (i < NN) ? g_cnt[i] : 0;
#pragma unroll
    for (int d = 16; d; d >>= 1) v += __shfl_xor_sync(0xffffffffu, v, d);
    if ((t & 31) == 0) ws[t >> 5] = v;
    __syncthreads();
    if (t < 8) {
        int s = ws[t];
#pragma unroll
        for (int d = 4; d; d >>= 1) s += __shfl_xor_sync(0xffu, s, d);
        if (t == 0) g_spine[blockIdx.x] = s;
    }
}

// per-block: spine prefix (computed locally) + intra-block scan + re-zero cnt
__global__ void k_s3() {
    __shared__ int ws[8];
    __shared__ int sbase;
    int t = threadIdx.x;
    int b = blockIdx.x;
    int acc = 0;
    for (int j = t; j < b; j += 256) acc += g_spine[j];
#pragma unroll
    for (int d = 16; d; d >>= 1) acc += __shfl_xor_sync(0xffffffffu, acc, d);
    if ((t & 31) == 0) ws[t >> 5] = acc;
    __syncthreads();
    if (t < 8) {
        int s = ws[t];
#pragma unroll
        for (int d = 4; d; d >>= 1) s += __shfl_xor_sync(0xffu, s, d);
        if (t == 0) sbase = s;
    }
    __syncthreads();
    int i = b * 256 + t;
    int orig = (i < NN) ? g_cnt[i] : 0;
    int v = orig;
#pragma unroll
    for (int d = 1; d < 32; d <<= 1) {
        int u = __shfl_up_sync(0xffffffffu, v, d);
        if ((t & 31) >= d) v += u;
    }
    if ((t & 31) == 31) ws[t >> 5] = v;
    __syncthreads();
    if (t < 8) {
        int s = ws[t];
#pragma unroll
        for (int d = 1; d < 8; d <<= 1) {
            int u = __shfl_up_sync(0xffu, s, d);
            if (t >= d) s += u;
        }
        ws[t] = s;
    }
    __syncthreads();
    int incl = v + ((t >= 32) ? ws[(t >> 5) - 1] : 0);
    int excl = incl - orig + sbase;
    if (i < NN) { g_off[i] = excl; g_pos[i] = excl; g_cnt[i] = 0; }
    if (b == SB - 1 && t == 255) g_off[NN] = NE;
}

__global__ void k_scatter(const void* __restrict__ ei) {
    __shared__ int sis64;
    int is64 = detect_is64_block(ei, &sis64);
    int e = blockIdx.x * blockDim.x + threadIdx.x;
    if (e >= NE) return;
    int s, d;
    if (is64) {
        const long long* p = (const long long*)ei;
        s = (int)p[e]; d = (int)p[NE + e];
    } else {
        const int* p = (const int*)ei;
        s = p[e]; d = p[NE + e];
    }
    int pos = atomicAdd(&g_pos[d], 1);
    g_adj[pos] = s;
}

// ---------------- tensor-core GEMM + fused alpha ------------------------------
// 256 threads (8 warps), 128 nodes/block. bf16 mma.sync m16n8k16, fp32 accum.
template <bool FIRST, int H>
__global__ void __launch_bounds__(256) k_gemm(const float* __restrict__ W,
                       const float* __restrict__ ue,
                       const float* __restrict__ ie,
                       const float* __restrict__ a_src,
                       const float* __restrict__ a_dst) {
    __shared__ __nv_bfloat16 sW[64][72];
    __shared__ __nv_bfloat16 sX[128][72];
    int t = threadIdx.x;
    int n0 = blockIdx.x * 128;

    {
        int r = t >> 2, cg = (t & 3) * 16;
#pragma unroll
        for (int i = 0; i < 4; i++) {
            float4 v = *(const float4*)&W[r * 64 + cg + i * 4];
            *(unsigned*)&sW[r][cg + i * 4 + 0] = f2bf2(v.x, v.y);
            *(unsigned*)&sW[r][cg + i * 4 + 2] = f2bf2(v.z, v.w);
        }
    }
    {
        int r = t >> 1, hf = (t & 1) * 32;
        int n = n0 + r;
        if (FIRST) {
            if (n < NN) {
                const float* row = (n < N_USERS) ? ue + (size_t)n * 64
                                                 : ie + (size_t)(n - N_USERS) * 64;
#pragma unroll
                for (int i = 0; i < 8; i++) {
                    float4 v = *(const float4*)&row[hf + i * 4];
                    *(unsigned*)&sX[r][hf + i * 4 + 0] = f2bf2(v.x, v.y);
                    *(unsigned*)&sX[r][hf + i * 4 + 2] = f2bf2(v.z, v.w);
                }
            } else {
#pragma unroll
                for (int i = 0; i < 16; i++) *(unsigned*)&sX[r][hf + i * 2] = 0u;
            }
        } else {
            if (n < NN) {
                const uint4* src = (const uint4*)&g_xb[(size_t)n * 64 + hf];
#pragma unroll
                for (int i = 0; i < 4; i++) *(uint4*)&sX[r][hf + i * 8] = src[i];
            } else {
#pragma unroll
                for (int i = 0; i < 16; i++) *(unsigned*)&sX[r][hf + i * 2] = 0u;
            }
        }
    }
    __syncthreads();

    int wid = t >> 5, lane = t & 31;
    int m0 = wid * 16;
    int grp = lane >> 3, li = lane & 7;

    unsigned afr[4][4];
    {
        int row = m0 + ((grp & 1) ? 8 : 0) + li;
#pragma unroll
        for (int kc = 0; kc < 4; kc++) {
            int col = kc * 16 + ((grp & 2) ? 8 : 0);
            ldsm_x4(afr[kc], smaddr(&sX[row][col]));
        }
    }
    float cfr[8][4];
#pragma unroll
    for (int nt = 0; nt < 8; nt++)
#pragma unroll
        for (int q = 0; q < 4; q++) cfr[nt][q] = 0.f;
    {
        int brow = lane & 15;
#pragma unroll
        for (int nt = 0; nt < 8; nt++) {
#pragma unroll
            for (int kc = 0; kc < 4; kc++) {
                unsigned bfr[2];
                ldsm_x2t(bfr, smaddr(&sW[kc * 16 + brow][nt * 8]));
                mma_bf16(cfr[nt], afr[kc], bfr);
            }
        }
    }
    {
        int r = m0 + (lane >> 2);
        int cbase = (lane & 3) * 2;
#pragma unroll
        for (int nt = 0; nt < 8; nt++) {
            int c = nt * 8 + cbase;
            *(unsigned*)&sX[r][c]     = f2bf2(cfr[nt][0], cfr[nt][1]);
            *(unsigned*)&sX[r + 8][c] = f2bf2(cfr[nt][2], cfr[nt][3]);
        }
    }
    __syncthreads();

    {
        int nb = t >> 1, hf = (t & 1) * 32;
        int n = n0 + nb;
        uint4 v0 = *(const uint4*)&sX[nb][hf];
        uint4 v1 = *(const uint4*)&sX[nb][hf + 8];
        uint4 v2 = *(const uint4*)&sX[nb][hf + 16];
        uint4 v3 = *(const uint4*)&sX[nb][hf + 24];
        if (n < NN) {
            uint4* dst = (uint4*)&g_hb[(size_t)n * 64 + hf];
            dst[0] = v0; dst[1] = v1; dst[2] = v2; dst[3] = v3;
        }
        unsigned hw[16] = { v0.x, v0.y, v0.z, v0.w, v1.x, v1.y, v1.z, v1.w,
                            v2.x, v2.y, v2.z, v2.w, v3.x, v3.y, v3.z, v3.w };
        if (H == 4) {
            float ps0 = 0.f, pd0 = 0.f, ps1 = 0.f, pd1 = 0.f;
#pragma unroll
            for (int i = 0; i < 8; i++) {
                float2 hv = bf2f(hw[i]);
                int c = hf + i * 2;
                ps0 += hv.x * a_src[c] + hv.y * a_src[c + 1];
                pd0 += hv.x * a_dst[c] + hv.y * a_dst[c + 1];
            }
#pragma unroll
            for (int i = 8; i < 16; i++) {
                float2 hv = bf2f(hw[i]);
                int c = hf + i * 2;
                ps1 += hv.x * a_src[c] + hv.y * a_src[c + 1];
                pd1 += hv.x * a_dst[c] + hv.y * a_dst[c + 1];
            }
            if (n < NN) {
                int h0 = hf / 16;
                g_as[n * 4 + h0]     = ps0;
                g_ad[n * 4 + h0]     = pd0;
                g_as[n * 4 + h0 + 1] = ps1;
                g_ad[n * 4 + h0 + 1] = pd1;
            }
        } else {
            float ps = 0.f, pd = 0.f;
#pragma unroll
            for (int i = 0; i < 16; i++) {
                float2 hv = bf2f(hw[i]);
                int c = hf + i * 2;
                ps += hv.x * a_src[c] + hv.y * a_src[c + 1];
                pd += hv.x * a_dst[c] + hv.y * a_dst[c + 1];
            }
            ps += __shfl_xor_sync(0xffffffffu, ps, 1);
            pd += __shfl_xor_sync(0xffffffffu, pd, 1);
            if (n < NN && (t & 1) == 0) { g_as[n] = ps; g_ad[n] = pd; }
        }
    }
}

// ---------------- fused aggregation (round-7 shape, reordered loads) ---------
// 4 nodes/warp, 8 lanes/node, lane owns 8 cols. h-row gathers (longest latency,
// dependent only on adj) are issued BEFORE the as-gather+exp stage.
template <int H, int F>
__global__ void k_agg(const float* __restrict__ b) {
    int lane = threadIdx.x & 31;
    int wrp  = threadIdx.x >> 5;
    int quad = lane >> 3;
    int l    = lane & 7;
    int n    = blockIdx.x * 32 + wrp * 4 + quad;
    if (n >= NN) return;
    int c0   = l * 8;
    int head = c0 / F;

    float ad_d = __ldg(&g_ad[(size_t)n * H + head]);
    float den  = __expf(lrelu(__ldg(&g_as[(size_t)n * H + head]) + ad_d));
    const uint4* hb = (const uint4*)g_hb;
    uint4 hs = hb[(size_t)n * 8 + l];
    float2 h01 = bf2f(hs.x), h23 = bf2f(hs.y), h45 = bf2f(hs.z), h67 = bf2f(hs.w);
    float a0 = den * h01.x, a1 = den * h01.y, a2 = den * h23.x, a3 = den * h23.y;
    float a4 = den * h45.x, a5 = den * h45.y, a6 = den * h67.x, a7 = den * h67.y;

    int beg = g_off[n], end = g_off[n + 1];
    int j = beg;
    for (; j + 4 <= end; j += 4) {
        int s[4]; float w[4]; uint4 p[4];
#pragma unroll
        for (int q = 0; q < 4; q++) s[q] = __ldg(&g_adj[j + q]);
#pragma unroll
        for (int q = 0; q < 4; q++) p[q] = hb[(size_t)s[q] * 8 + l];   // issue h first
#pragma unroll
        for (int q = 0; q < 4; q++)
            w[q] = __expf(lrelu(__ldg(&g_as[(size_t)s[q] * H + head]) + ad_d));
#pragma unroll
        for (int q = 0; q < 4; q++) {
            float2 q01 = bf2f(p[q].x), q23 = bf2f(p[q].y);
            float2 q45 = bf2f(p[q].z), q67 = bf2f(p[q].w);
            den += w[q];
            a0 += w[q] * q01.x; a1 += w[q] * q01.y;
            a2 += w[q] * q23.x; a3 += w[q] * q23.y;
            a4 += w[q] * q45.x; a5 += w[q] * q45.y;
            a6 += w[q] * q67.x; a7 += w[q] * q67.y;
        }
    }
    for (; j < end; j++) {
        int s = __ldg(&g_adj[j]);
        uint4 p = hb[(size_t)s * 8 + l];
        float w = __expf(lrelu(__ldg(&g_as[(size_t)s * H + head]) + ad_d));
        float2 q01 = bf2f(p.x), q23 = bf2f(p.y), q45 = bf2f(p.z), q67 = bf2f(p.w);
        den += w;
        a0 += w * q01.x; a1 += w * q01.y; a2 += w * q23.x; a3 += w * q23.y;
        a4 += w * q45.x; a5 += w * q45.y; a6 += w * q67.x; a7 += w * q67.y;
    }
    float inv = 1.f / den;
    uint4 o;
    o.x = f2bf2(eluf(a0 * inv + b[c0 + 0]), eluf(a1 * inv + b[c0 + 1]));
    o.y = f2bf2(eluf(a2 * inv + b[c0 + 2]), eluf(a3 * inv + b[c0 + 3]));
    o.z = f2bf2(eluf(a4 * inv + b[c0 + 4]), eluf(a5 * inv + b[c0 + 5]));
    o.w = f2bf2(eluf(a6 * inv + b[c0 + 6]), eluf(a7 * inv + b[c0 + 7]));
    *(uint4*)&g_xb[(size_t)n * 64 + c0] = o;
}

// ---------------- final scoring (bf16 features) -------------------------------
__global__ void k_score(const void* __restrict__ bu_, const void* __restrict__ bi_,
                        float* __restrict__ out) {
    __shared__ int sis64;
    int is64 = detect_is64_block(bu_, &sis64);
    int gid = blockIdx.x * blockDim.x + threadIdx.x;
    if (gid >= NB * 8) return;
    int p = gid >> 3, l = gid & 7;
    int u, it;
    if (is64) {
        u  = (int)((const long long*)bu_)[p];
        it = (int)((const long long*)bi_)[p];
    } else {
        u  = ((const int*)bu_)[p];
        it = ((const int*)bi_)[p];
    }
    const uint4* xb = (const uint4*)g_xb;
    uint4 av = xb[(size_t)u * 8 + l];
    uint4 bv = xb[((size_t)it + N_USERS) * 8 + l];
    float acc;
    {
        float2 a01 = bf2f(av.x), b01 = bf2f(bv.x);
        float2 a23 = bf2f(av.y), b23 = bf2f(bv.y);
        float2 a45 = bf2f(av.z), b45 = bf2f(bv.z);
        float2 a67 = bf2f(av.w), b67 = bf2f(bv.w);
        acc = a01.x * b01.x + a01.y * b01.y + a23.x * b23.x + a23.y * b23.y
            + a45.x * b45.x + a45.y * b45.y + a67.x * b67.x + a67.y * b67.y;
    }
    acc += __shfl_xor_sync(0xffffffffu, acc, 1);
    acc += __shfl_xor_sync(0xffffffffu, acc, 2);
    acc += __shfl_xor_sync(0xffffffffu, acc, 4);
    if (l == 0) out[p] = 1.f / (1.f + expf(-acc));
}

// ---------------- host launcher ----------------------------------------------
extern "C" void kernel_launch(void* const* d_in, const int* in_sizes, int n_in,
                              void* d_out, int out_size) {
    const void *edge = nullptr, *bu = nullptr, *bi = nullptr;
    const float *ue = nullptr, *ie = nullptr, *W1 = nullptr, *W2 = nullptr;
    const float* v64[6] = {nullptr, nullptr, nullptr, nullptr, nullptr, nullptr};
    int c64 = 0;
    for (int i = 0; i < n_in; i++) {
        int sz = in_sizes[i];
        if      (sz == 2 * NE)        edge = d_in[i];
        else if (sz == NB)            { if (!bu) bu = d_in[i]; else bi = d_in[i]; }
        else if (sz == N_USERS * DD)  ue = (const float*)d_in[i];
        else if (sz == N_ITEMS * DD)  ie = (const float*)d_in[i];
        else if (sz == DD * DD)       { if (!W1) W1 = (const float*)d_in[i];
                                        else     W2 = (const float*)d_in[i]; }
        else if (sz == 64 && c64 < 6) v64[c64++] = (const float*)d_in[i];
    }
    const float *as1 = v64[0], *ad1 = v64[1], *b1 = v64[2];
    const float *as2 = v64[3], *ad2 = v64[4], *b2 = v64[5];

    const int TB = 256;
    const int EB = (NE + TB - 1) / TB;
    const int GB = (NN + 127) / 128;

    // secondary stream + events for overlapping gemm1 with the CSR build.
    static cudaStream_t s2 = nullptr;
    static cudaEvent_t  evA = nullptr, evB = nullptr;
    static int init_done = 0;
    if (!init_done) {
        if (cudaStreamCreateWithFlags(&s2, cudaStreamNonBlocking) != cudaSuccess) s2 = nullptr;
        if (cudaEventCreateWithFlags(&evA, cudaEventDisableTiming) != cudaSuccess) evA = nullptr;
        if (cudaEventCreateWithFlags(&evB, cudaEventDisableTiming) != cudaSuccess) evB = nullptr;
        init_done = 1;
    }

    bool fork = false;
    if (s2 && evA && evB) {
        if (cudaEventRecord(evA, 0) == cudaSuccess &&
            cudaStreamWaitEvent(s2, evA, 0) == cudaSuccess)
            fork = true;
    }

    if (fork) {
        k_gemm<true, 4><<<GB, 256, 0, s2>>>(W1, ue, ie, as1, ad1);
        if (cudaEventRecord(evB, s2) != cudaSuccess) fork = false;
    }

    // CSR build chain (stream 0)
    k_count  <<<EB, TB>>>(edge);
    k_s1     <<<SB, 256>>>();
    k_s3     <<<SB, 256>>>();
    k_scatter<<<EB, TB>>>(edge);

    if (fork) {
        cudaStreamWaitEvent(0, evB, 0);
    } else {
        k_gemm<true, 4><<<GB, 256>>>(W1, ue, ie, as1, ad1);
    }

    k_agg <4, 16>   <<<(NN + 31) / 32, TB>>>(b1);
    k_gemm<false, 1><<<GB, 256>>>(W2, nullptr, nullptr, as2, ad2);
    k_agg <1, 64>   <<<(NN + 31) / 32, TB>>>(b2);
    k_score<<<(NB * 8 + TB - 1) / TB, TB>>>(bu, bi, (float*)d_out);
}

// round 16
// speedup vs baseline: 1.0486x; 1.0486x over previous
#include <cuda_runtime.h>
#include <cuda_bf16.h>
#include <cuda_fp16.h>

#define N_USERS 100000
#define N_ITEMS 50000
#define NN      150000
#define NE      2000000
#define DD      64
#define NB      16384
#define SB      586      // ceil(NN/256) scan blocks

// ---------------- scratch (device globals) ----------------------------------
__device__ __nv_bfloat16  g_xb[NN*DD];    // layer outputs (bf16)
__device__ unsigned char  g_h8[NN*DD];    // h payload in fp8 e4m3, scaled x256
__device__ float g_as [NN*4];
__device__ float g_ad [NN*4];
__device__ int   g_adj[NE];
__device__ int   g_cnt[NN];               // zero at entry (re-zeroed in k_scan)
__device__ int   g_off[NN+1];
__device__ int   g_pos[NN];
__device__ int   g_spine[1024];
__device__ int   g_flag[SB];              // zero at entry (re-zeroed in k_scatter)

#define H8_SCALE 256.f
#define H8_INVSC (1.f/256.f)

// ---------------- helpers ---------------------------------------------------
__device__ __forceinline__ float lrelu(float x) { return x > 0.f ? x : 0.2f * x; }
__device__ __forceinline__ float eluf (float v) { return v > 0.f ? v : expf(v) - 1.f; }
__device__ __forceinline__ float2 bf2f(unsigned u) {
    return __bfloat1622float2(*(__nv_bfloat162*)&u);
}
__device__ __forceinline__ unsigned f2bf2(float a, float b) {
    __nv_bfloat162 p = __float22bfloat162_rn(make_float2(a, b));
    return *(unsigned*)&p;
}
// pack two floats into e4m3x2 (lo = first arg)
__device__ __forceinline__ unsigned short f2fp8(float lo, float hi) {
    unsigned short r;
    asm("cvt.rn.satfinite.e4m3x2.f32 %0, %1, %2;" : "=h"(r) : "f"(hi), "f"(lo));
    return r;
}
// unpack 4 fp8 (one u32) -> two float2 (lo bytes first)
__device__ __forceinline__ void fp8x4_f32(unsigned v, float2& lo, float2& hi) {
    unsigned h0, h1;
    unsigned short s0 = (unsigned short)v, s1 = (unsigned short)(v >> 16);
    asm("cvt.rn.f16x2.e4m3x2 %0, %1;" : "=r"(h0) : "h"(s0));
    asm("cvt.rn.f16x2.e4m3x2 %0, %1;" : "=r"(h1) : "h"(s1));
    lo = __half22float2(*(__half2*)&h0);
    hi = __half22float2(*(__half2*)&h1);
}
__device__ __forceinline__ unsigned smaddr(const void* p) {
    return (unsigned)__cvta_generic_to_shared(p);
}
__device__ __forceinline__ void ldsm_x4(unsigned* r, unsigned a) {
    asm volatile("ldmatrix.sync.aligned.m8n8.x4.shared.b16 {%0,%1,%2,%3}, [%4];"
                 : "=r"(r[0]), "=r"(r[1]), "=r"(r[2]), "=r"(r[3]) : "r"(a));
}
__device__ __forceinline__ void ldsm_x2t(unsigned* r, unsigned a) {
    asm volatile("ldmatrix.sync.aligned.m8n8.x2.trans.shared.b16 {%0,%1}, [%2];"
                 : "=r"(r[0]), "=r"(r[1]) : "r"(a));
}
__device__ __forceinline__ void mma_bf16(float* c, const unsigned* a, const unsigned* b) {
    asm volatile("mma.sync.aligned.m16n8k16.row.col.f32.bf16.bf16.f32 "
                 "{%0,%1,%2,%3}, {%4,%5,%6,%7}, {%8,%9}, {%0,%1,%2,%3};"
                 : "+f"(c[0]), "+f"(c[1]), "+f"(c[2]), "+f"(c[3])
                 : "r"(a[0]), "r"(a[1]), "r"(a[2]), "r"(a[3]),
                   "r"(b[0]), "r"(b[1]));
}

// per-block int64-vs-int32 detection (node ids << 2^31)
__device__ __forceinline__ int detect_is64_block(const void* ei, int* sflag) {
    int t = threadIdx.x;
    if (t < 32) {
        const int* p = (const int*)ei;
        int v = p[2 * t + 1] | p[2 * (t + 32) + 1];
        unsigned b = __ballot_sync(0xffffffffu, v != 0);
        if (t == 0) *sflag = (b == 0);
    }
    __syncthreads();
    return *sflag;
}

// ---------------- CSR build ----------------------------------------------------
__global__ void k_count(const void* __restrict__ ei) {
    __shared__ int sis64;
    int is64 = detect_is64_block(ei, &sis64);
    int e = blockIdx.x * blockDim.x + threadIdx.x;
    if (e >= NE) return;
    int d = is64 ? (int)((const long long*)ei)[NE + e]
                 : ((const int*)ei)[NE + e];
    atomicAdd(&g_cnt[d], 1);
}

// single-pass exclusive scan (decoupled aggregate lookback; all 586 blocks
// are co-resident so publish-before-poll cannot deadlock)
__global__ void k_scan() {
    __shared__ int ws[8];
    __shared__ int sbase;
    int t = threadIdx.x, b = blockIdx.x;
    int i = b * 256 + t;
    int orig = (i < NN) ? g_cnt[i] : 0;
    // 1) block aggregate -> publish
    int v = orig;
#pragma unroll
    for (int d = 16; d; d >>= 1) v += __shfl_xor_sync(0xffffffffu, v, d);
    if ((t & 31) == 0) ws[t >> 5] = v;
    __syncthreads();
    if (t < 8) {
        int s = ws[t];
#pragma unroll
        for (int d = 4; d; d >>= 1) s += __shfl_xor_sync(0xffu, s, d);
        if (t == 0) {
            g_spine[b] = s;
            __threadfence();
            atomicExch(&g_flag[b], 1);
        }
    }
    __syncthreads();
    // 2) sum predecessors' aggregates
    int acc = 0;
    for (int j = t; j < b; j += 256) {
        while (((volatile int*)g_flag)[j] == 0) { }
        acc += ((volatile int*)g_spine)[j];
    }
#pragma unroll
    for (int d = 16; d; d >>= 1) acc += __shfl_xor_sync(0xffffffffu, acc, d);
    if ((t & 31) == 0) ws[t >> 5] = acc;
    __syncthreads();
    if (t < 8) {
        int s = ws[t];
#pragma unroll
        for (int d = 4; d; d >>= 1) s += __shfl_xor_sync(0xffu, s, d);
        if (t == 0) sbase = s;
    }
    __syncthreads();
    // 3) intra-block exclusive scan
    int vv = orig;
#pragma unroll
    for (int d = 1; d < 32; d <<= 1) {
        int u = __shfl_up_sync(0xffffffffu, vv, d);
        if ((t & 31) >= d) vv += u;
    }
    if ((t & 31) == 31) ws[t >> 5] = vv;
    __syncthreads();
    if (t < 8) {
        int s = ws[t];
#pragma unroll
        for (int d = 1; d < 8; d <<= 1) {
            int u = __shfl_up_sync(0xffu, s, d);
            if (t >= d) s += u;
        }
        ws[t] = s;
    }
    __syncthreads();
    int incl = vv + ((t >= 32) ? ws[(t >> 5) - 1] : 0);
    int excl = incl - orig + sbase;
    if (i < NN) { g_off[i] = excl; g_pos[i] = excl; g_cnt[i] = 0; }
    if (b == SB - 1 && t == 255) g_off[NN] = NE;
}

__global__ void k_scatter(const void* __restrict__ ei) {
    __shared__ int sis64;
    int is64 = detect_is64_block(ei, &sis64);
    int e = blockIdx.x * blockDim.x + threadIdx.x;
    if (e < SB) g_flag[e] = 0;          // reset lookback flags for next replay
    if (e >= NE) return;
    int s, d;
    if (is64) {
        const long long* p = (const long long*)ei;
        s = (int)p[e]; d = (int)p[NE + e];
    } else {
        const int* p = (const int*)ei;
        s = p[e]; d = p[NE + e];
    }
    int pos = atomicAdd(&g_pos[d], 1);
    g_adj[pos] = s;
}

// ---------------- tensor-core GEMM + fused alpha ------------------------------
// 256 threads (8 warps), 128 nodes/block. bf16 mma.sync m16n8k16, fp32 accum.
// Writes fp8 payload (x256) + fp32 alpha logits.
template <bool FIRST, int H>
__global__ void __launch_bounds__(256) k_gemm(const float* __restrict__ W,
                       const float* __restrict__ ue,
                       const float* __restrict__ ie,
                       const float* __restrict__ a_src,
                       const float* __restrict__ a_dst) {
    __shared__ __nv_bfloat16 sW[64][72];
    __shared__ __nv_bfloat16 sX[128][72];
    int t = threadIdx.x;
    int n0 = blockIdx.x * 128;

    {
        int r = t >> 2, cg = (t & 3) * 16;
#pragma unroll
        for (int i = 0; i < 4; i++) {
            float4 v = *(const float4*)&W[r * 64 + cg + i * 4];
            *(unsigned*)&sW[r][cg + i * 4 + 0] = f2bf2(v.x, v.y);
            *(unsigned*)&sW[r][cg + i * 4 + 2] = f2bf2(v.z, v.w);
        }
    }
    {
        int r = t >> 1, hf = (t & 1) * 32;
        int n = n0 + r;
        if (FIRST) {
            if (n < NN) {
                const float* row = (n < N_USERS) ? ue + (size_t)n * 64
                                                 : ie + (size_t)(n - N_USERS) * 64;
#pragma unroll
                for (int i = 0; i < 8; i++) {
                    float4 v = *(const float4*)&row[hf + i * 4];
                    *(unsigned*)&sX[r][hf + i * 4 + 0] = f2bf2(v.x, v.y);
                    *(unsigned*)&sX[r][hf + i * 4 + 2] = f2bf2(v.z, v.w);
                }
            } else {
#pragma unroll
                for (int i = 0; i < 16; i++) *(unsigned*)&sX[r][hf + i * 2] = 0u;
            }
        } else {
            if (n < NN) {
                const uint4* src = (const uint4*)&g_xb[(size_t)n * 64 + hf];
#pragma unroll
                for (int i = 0; i < 4; i++) *(uint4*)&sX[r][hf + i * 8] = src[i];
            } else {
#pragma unroll
                for (int i = 0; i < 16; i++) *(unsigned*)&sX[r][hf + i * 2] = 0u;
            }
        }
    }
    __syncthreads();

    int wid = t >> 5, lane = t & 31;
    int m0 = wid * 16;
    int grp = lane >> 3, li = lane & 7;

    unsigned afr[4][4];
    {
        int row = m0 + ((grp & 1) ? 8 : 0) + li;
#pragma unroll
        for (int kc = 0; kc < 4; kc++) {
            int col = kc * 16 + ((grp & 2) ? 8 : 0);
            ldsm_x4(afr[kc], smaddr(&sX[row][col]));
        }
    }
    float cfr[8][4];
#pragma unroll
    for (int nt = 0; nt < 8; nt++)
#pragma unroll
        for (int q = 0; q < 4; q++) cfr[nt][q] = 0.f;
    {
        int brow = lane & 15;
#pragma unroll
        for (int nt = 0; nt < 8; nt++) {
#pragma unroll
            for (int kc = 0; kc < 4; kc++) {
                unsigned bfr[2];
                ldsm_x2t(bfr, smaddr(&sW[kc * 16 + brow][nt * 8]));
                mma_bf16(cfr[nt], afr[kc], bfr);
            }
        }
    }
    {
        int r = m0 + (lane >> 2);
        int cbase = (lane & 3) * 2;
#pragma unroll
        for (int nt = 0; nt < 8; nt++) {
            int c = nt * 8 + cbase;
            *(unsigned*)&sX[r][c]     = f2bf2(cfr[nt][0], cfr[nt][1]);
            *(unsigned*)&sX[r + 8][c] = f2bf2(cfr[nt][2], cfr[nt][3]);
        }
    }
    __syncthreads();

    {
        int nb = t >> 1, hf = (t & 1) * 32;
        int n = n0 + nb;
        uint4 v0 = *(const uint4*)&sX[nb][hf];
        uint4 v1 = *(const uint4*)&sX[nb][hf + 8];
        uint4 v2 = *(const uint4*)&sX[nb][hf + 16];
        uint4 v3 = *(const uint4*)&sX[nb][hf + 24];
        unsigned hw[16] = { v0.x, v0.y, v0.z, v0.w, v1.x, v1.y, v1.z, v1.w,
                            v2.x, v2.y, v2.z, v2.w, v3.x, v3.y, v3.z, v3.w };
        // fp8 payload (scaled)
        if (n < NN) {
            unsigned u[8];
#pragma unroll
            for (int jj = 0; jj < 8; jj++) {
                float2 e0 = bf2f(hw[2 * jj]);
                float2 e1 = bf2f(hw[2 * jj + 1]);
                unsigned short p0 = f2fp8(e0.x * H8_SCALE, e0.y * H8_SCALE);
                unsigned short p1 = f2fp8(e1.x * H8_SCALE, e1.y * H8_SCALE);
                u[jj] = (unsigned)p0 | ((unsigned)p1 << 16);
            }
            uint4* dst = (uint4*)&g_h8[(size_t)n * 64 + hf];
            dst[0] = make_uint4(u[0], u[1], u[2], u[3]);
            dst[1] = make_uint4(u[4], u[5], u[6], u[7]);
        }
        // alpha logits (fp32)
        if (H == 4) {
            float ps0 = 0.f, pd0 = 0.f, ps1 = 0.f, pd1 = 0.f;
#pragma unroll
            for (int i = 0; i < 8; i++) {
                float2 hv = bf2f(hw[i]);
                int c = hf + i * 2;
                ps0 += hv.x * a_src[c] + hv.y * a_src[c + 1];
                pd0 += hv.x * a_dst[c] + hv.y * a_dst[c + 1];
            }
#pragma unroll
            for (int i = 8; i < 16; i++) {
                float2 hv = bf2f(hw[i]);
                int c = hf + i * 2;
                ps1 += hv.x * a_src[c] + hv.y * a_src[c + 1];
                pd1 += hv.x * a_dst[c] + hv.y * a_dst[c + 1];
            }
            if (n < NN) {
                int h0 = hf / 16;
                g_as[n * 4 + h0]     = ps0;
                g_ad[n * 4 + h0]     = pd0;
                g_as[n * 4 + h0 + 1] = ps1;
                g_ad[n * 4 + h0 + 1] = pd1;
            }
        } else {
            float ps = 0.f, pd = 0.f;
#pragma unroll
            for (int i = 0; i < 16; i++) {
                float2 hv = bf2f(hw[i]);
                int c = hf + i * 2;
                ps += hv.x * a_src[c] + hv.y * a_src[c + 1];
                pd += hv.x * a_dst[c] + hv.y * a_dst[c + 1];
            }
            ps += __shfl_xor_sync(0xffffffffu, ps, 1);
            pd += __shfl_xor_sync(0xffffffffu, pd, 1);
            if (n < NN && (t & 1) == 0) { g_as[n] = ps; g_ad[n] = pd; }
        }
    }
}

// ---------------- fused aggregation (fp8 payload gathers) --------------------
// 4 nodes/warp, 8 lanes/node, lane owns 8 cols (uint2 = 8 fp8; full row = 64B).
template <int H, int F>
__global__ void k_agg(const float* __restrict__ b) {
    int lane = threadIdx.x & 31;
    int wrp  = threadIdx.x >> 5;
    int quad = lane >> 3;
    int l    = lane & 7;
    int n    = blockIdx.x * 32 + wrp * 4 + quad;
    if (n >= NN) return;
    int c0   = l * 8;
    int head = c0 / F;

    float ad_d = __ldg(&g_ad[(size_t)n * H + head]);
    float den  = __expf(lrelu(__ldg(&g_as[(size_t)n * H + head]) + ad_d));
    const uint2* h8 = (const uint2*)g_h8;   // row = 8 uint2 (64 fp8)
    uint2 hs = h8[(size_t)n * 8 + l];
    float2 f0, f1, f2, f3;
    fp8x4_f32(hs.x, f0, f1);
    fp8x4_f32(hs.y, f2, f3);
    float a0 = den * f0.x, a1 = den * f0.y, a2 = den * f1.x, a3 = den * f1.y;
    float a4 = den * f2.x, a5 = den * f2.y, a6 = den * f3.x, a7 = den * f3.y;

    int beg = g_off[n], end = g_off[n + 1];
    int j = beg;
    for (; j + 4 <= end; j += 4) {
        int s[4]; float w[4]; uint2 p[4];
#pragma unroll
        for (int q = 0; q < 4; q++) s[q] = __ldg(&g_adj[j + q]);
#pragma unroll
        for (int q = 0; q < 4; q++) p[q] = h8[(size_t)s[q] * 8 + l];
#pragma unroll
        for (int q = 0; q < 4; q++)
            w[q] = __expf(lrelu(__ldg(&g_as[(size_t)s[q] * H + head]) + ad_d));
#pragma unroll
        for (int q = 0; q < 4; q++) {
            float2 q0, q1, q2, q3;
            fp8x4_f32(p[q].x, q0, q1);
            fp8x4_f32(p[q].y, q2, q3);
            den += w[q];
            a0 += w[q] * q0.x; a1 += w[q] * q0.y;
            a2 += w[q] * q1.x; a3 += w[q] * q1.y;
            a4 += w[q] * q2.x; a5 += w[q] * q2.y;
            a6 += w[q] * q3.x; a7 += w[q] * q3.y;
        }
    }
    for (; j < end; j++) {
        int s = __ldg(&g_adj[j]);
        uint2 p = h8[(size_t)s * 8 + l];
        float w = __expf(lrelu(__ldg(&g_as[(size_t)s * H + head]) + ad_d));
        float2 q0, q1, q2, q3;
        fp8x4_f32(p.x, q0, q1);
        fp8x4_f32(p.y, q2, q3);
        den += w;
        a0 += w * q0.x; a1 += w * q0.y; a2 += w * q1.x; a3 += w * q1.y;
        a4 += w * q2.x; a5 += w * q2.y; a6 += w * q3.x; a7 += w * q3.y;
    }
    float inv = 1.f / (den * H8_SCALE);   // undo payload scale once
    uint4 o;
    o.x = f2bf2(eluf(a0 * inv + b[c0 + 0]), eluf(a1 * inv + b[c0 + 1]));
    o.y = f2bf2(eluf(a2 * inv + b[c0 + 2]), eluf(a3 * inv + b[c0 + 3]));
    o.z = f2bf2(eluf(a4 * inv + b[c0 + 4]), eluf(a5 * inv + b[c0 + 5]));
    o.w = f2bf2(eluf(a6 * inv + b[c0 + 6]), eluf(a7 * inv + b[c0 + 7]));
    *(uint4*)&g_xb[(size_t)n * 64 + c0] = o;
}

// ---------------- final scoring (bf16 features) -------------------------------
__global__ void k_score(const void* __restrict__ bu_, const void* __restrict__ bi_,
                        float* __restrict__ out) {
    __shared__ int sis64;
    int is64 = detect_is64_block(bu_, &sis64);
    int gid = blockIdx.x * blockDim.x + threadIdx.x;
    if (gid >= NB * 8) return;
    int p = gid >> 3, l = gid & 7;
    int u, it;
    if (is64) {
        u  = (int)((const long long*)bu_)[p];
        it = (int)((const long long*)bi_)[p];
    } else {
        u  = ((const int*)bu_)[p];
        it = ((const int*)bi_)[p];
    }
    const uint4* xb = (const uint4*)g_xb;
    uint4 av = xb[(size_t)u * 8 + l];
    uint4 bv = xb[((size_t)it + N_USERS) * 8 + l];
    float acc;
    {
        float2 a01 = bf2f(av.x), b01 = bf2f(bv.x);
        float2 a23 = bf2f(av.y), b23 = bf2f(bv.y);
        float2 a45 = bf2f(av.z), b45 = bf2f(bv.z);
        float2 a67 = bf2f(av.w), b67 = bf2f(bv.w);
        acc = a01.x * b01.x + a01.y * b01.y + a23.x * b23.x + a23.y * b23.y
            + a45.x * b45.x + a45.y * b45.y + a67.x * b67.x + a67.y * b67.y;
    }
    acc += __shfl_xor_sync(0xffffffffu, acc, 1);
    acc += __shfl_xor_sync(0xffffffffu, acc, 2);
    acc += __shfl_xor_sync(0xffffffffu, acc, 4);
    if (l == 0) out[p] = 1.f / (1.f + expf(-acc));
}

// ---------------- host launcher ----------------------------------------------
extern "C" void kernel_launch(void* const* d_in, const int* in_sizes, int n_in,
                              void* d_out, int out_size) {
    const void *edge = nullptr, *bu = nullptr, *bi = nullptr;
    const float *ue = nullptr, *ie = nullptr, *W1 = nullptr, *W2 = nullptr;
    const float* v64[6] = {nullptr, nullptr, nullptr, nullptr, nullptr, nullptr};
    int c64 = 0;
    for (int i = 0; i < n_in; i++) {
        int sz = in_sizes[i];
        if      (sz == 2 * NE)        edge = d_in[i];
        else if (sz == NB)            { if (!bu) bu = d_in[i]; else bi = d_in[i]; }
        else if (sz == N_USERS * DD)  ue = (const float*)d_in[i];
        else if (sz == N_ITEMS * DD)  ie = (const float*)d_in[i];
        else if (sz == DD * DD)       { if (!W1) W1 = (const float*)d_in[i];
                                        else     W2 = (const float*)d_in[i]; }
        else if (sz == 64 && c64 < 6) v64[c64++] = (const float*)d_in[i];
    }
    const float *as1 = v64[0], *ad1 = v64[1], *b1 = v64[2];
    const float *as2 = v64[3], *ad2 = v64[4], *b2 = v64[5];

    const int TB = 256;
    const int EB = (NE + TB - 1) / TB;
    const int GB = (NN + 127) / 128;

    // secondary stream + events for overlapping gemm1 with the CSR build.
    static cudaStream_t s2 = nullptr;
    static cudaEvent_t  evA = nullptr, evB = nullptr;
    static int init_done = 0;
    if (!init_done) {
        if (cudaStreamCreateWithFlags(&s2, cudaStreamNonBlocking) != cudaSuccess) s2 = nullptr;
        if (cudaEventCreateWithFlags(&evA, cudaEventDisableTiming) != cudaSuccess) evA = nullptr;
        if (cudaEventCreateWithFlags(&evB, cudaEventDisableTiming) != cudaSuccess) evB = nullptr;
        init_done = 1;
    }

    bool fork = false;
    if (s2 && evA && evB) {
        if (cudaEventRecord(evA, 0) == cudaSuccess &&
            cudaStreamWaitEvent(s2, evA, 0) == cudaSuccess)
            fork = true;
    }

    if (fork) {
        k_gemm<true, 4><<<GB, 256, 0, s2>>>(W1, ue, ie, as1, ad1);
        if (cudaEventRecord(evB, s2) != cudaSuccess) fork = false;
    }

    // CSR build chain (stream 0)
    k_count  <<<EB, TB>>>(edge);
    k_scan   <<<SB, 256>>>();
    k_scatter<<<EB, TB>>>(edge);

    if (fork) {
        cudaStreamWaitEvent(0, evB, 0);
    } else {
        k_gemm<true, 4><<<GB, 256>>>(W1, ue, ie, as1, ad1);
    }

    k_agg <4, 16>   <<<(NN + 31) / 32, TB>>>(b1);
    k_gemm<false, 1><<<GB, 256>>>(W2, nullptr, nullptr, as2, ad2);
    k_agg <1, 64>   <<<(NN + 31) / 32, TB>>>(b2);
    k_score<<<(NB * 8 + TB - 1) / TB, TB>>>(bu, bi, (float*)d_out);
}

// round 17
// speedup vs baseline: 1.0575x; 1.0086x over previous
#include <cuda_runtime.h>
#include <cuda_bf16.h>
#include <cuda_fp16.h>

#define N_USERS 100000
#define N_ITEMS 50000
#define NN      150000
#define NE      2000000
#define DD      64
#define NB      16384
#define SB      586      // ceil(NN/256) scan blocks

// ---------------- scratch (device globals) ----------------------------------
__device__ __nv_bfloat16  g_xb[NN*DD];    // layer outputs (bf16)
__device__ unsigned char  g_h8[NN*DD];    // h payload in fp8 e4m3, scaled x256
__device__ float g_as [NN*4];
__device__ float g_ad [NN*4];
__device__ int   g_adj[NE];
__device__ int   g_rank[NE];              // rank of edge within its dst bucket
__device__ int   g_cnt[NN];               // zero at entry (re-zeroed in k_scan)
__device__ int   g_off[NN+1];
__device__ int   g_spine[1024];
__device__ int   g_flag[SB];              // zero at entry (re-zeroed in k_scatter)

#define H8_SCALE 256.f

// ---------------- helpers ---------------------------------------------------
__device__ __forceinline__ float lrelu(float x) { return x > 0.f ? x : 0.2f * x; }
__device__ __forceinline__ float eluf (float v) { return v > 0.f ? v : expf(v) - 1.f; }
__device__ __forceinline__ float2 bf2f(unsigned u) {
    return __bfloat1622float2(*(__nv_bfloat162*)&u);
}
__device__ __forceinline__ unsigned f2bf2(float a, float b) {
    __nv_bfloat162 p = __float22bfloat162_rn(make_float2(a, b));
    return *(unsigned*)&p;
}
__device__ __forceinline__ unsigned short f2fp8(float lo, float hi) {
    unsigned short r;
    asm("cvt.rn.satfinite.e4m3x2.f32 %0, %1, %2;" : "=h"(r) : "f"(hi), "f"(lo));
    return r;
}
__device__ __forceinline__ void fp8x4_f32(unsigned v, float2& lo, float2& hi) {
    unsigned h0, h1;
    unsigned short s0 = (unsigned short)v, s1 = (unsigned short)(v >> 16);
    asm("cvt.rn.f16x2.e4m3x2 %0, %1;" : "=r"(h0) : "h"(s0));
    asm("cvt.rn.f16x2.e4m3x2 %0, %1;" : "=r"(h1) : "h"(s1));
    lo = __half22float2(*(__half2*)&h0);
    hi = __half22float2(*(__half2*)&h1);
}
__device__ __forceinline__ unsigned smaddr(const void* p) {
    return (unsigned)__cvta_generic_to_shared(p);
}
__device__ __forceinline__ void ldsm_x4(unsigned* r, unsigned a) {
    asm volatile("ldmatrix.sync.aligned.m8n8.x4.shared.b16 {%0,%1,%2,%3}, [%4];"
                 : "=r"(r[0]), "=r"(r[1]), "=r"(r[2]), "=r"(r[3]) : "r"(a));
}
__device__ __forceinline__ void ldsm_x2t(unsigned* r, unsigned a) {
    asm volatile("ldmatrix.sync.aligned.m8n8.x2.trans.shared.b16 {%0,%1}, [%2];"
                 : "=r"(r[0]), "=r"(r[1]) : "r"(a));
}
__device__ __forceinline__ void mma_bf16(float* c, const unsigned* a, const unsigned* b) {
    asm volatile("mma.sync.aligned.m16n8k16.row.col.f32.bf16.bf16.f32 "
                 "{%0,%1,%2,%3}, {%4,%5,%6,%7}, {%8,%9}, {%0,%1,%2,%3};"
                 : "+f"(c[0]), "+f"(c[1]), "+f"(c[2]), "+f"(c[3])
                 : "r"(a[0]), "r"(a[1]), "r"(a[2]), "r"(a[3]),
                   "r"(b[0]), "r"(b[1]));
}

// per-block int64-vs-int32 detection (node ids << 2^31)
__device__ __forceinline__ int detect_is64_block(const void* ei, int* sflag) {
    int t = threadIdx.x;
    if (t < 32) {
        const int* p = (const int*)ei;
        int v = p[2 * t + 1] | p[2 * (t + 32) + 1];
        unsigned b = __ballot_sync(0xffffffffu, v != 0);
        if (t == 0) *sflag = (b == 0);
    }
    __syncthreads();
    return *sflag;
}

// ---------------- CSR build ----------------------------------------------------
// count + rank: one atomic per edge, rank saved so scatter needs none.
__global__ void k_count(const void* __restrict__ ei) {
    __shared__ int sis64;
    int is64 = detect_is64_block(ei, &sis64);
    int e = blockIdx.x * blockDim.x + threadIdx.x;
    if (e >= NE) return;
    int d = is64 ? (int)((const long long*)ei)[NE + e]
                 : ((const int*)ei)[NE + e];
    g_rank[e] = atomicAdd(&g_cnt[d], 1);
}

// single-pass exclusive scan (decoupled aggregate lookback; all 586 blocks
// are co-resident so publish-before-poll cannot deadlock)
__global__ void k_scan() {
    __shared__ int ws[8];
    __shared__ int sbase;
    int t = threadIdx.x, b = blockIdx.x;
    int i = b * 256 + t;
    int orig = (i < NN) ? g_cnt[i] : 0;
    int v = orig;
#pragma unroll
    for (int d = 16; d; d >>= 1) v += __shfl_xor_sync(0xffffffffu, v, d);
    if ((t & 31) == 0) ws[t >> 5] = v;
    __syncthreads();
    if (t < 8) {
        int s = ws[t];
#pragma unroll
        for (int d = 4; d; d >>= 1) s += __shfl_xor_sync(0xffu, s, d);
        if (t == 0) {
            g_spine[b] = s;
            __threadfence();
            atomicExch(&g_flag[b], 1);
        }
    }
    __syncthreads();
    int acc = 0;
    for (int j = t; j < b; j += 256) {
        while (((volatile int*)g_flag)[j] == 0) { }
        acc += ((volatile int*)g_spine)[j];
    }
#pragma unroll
    for (int d = 16; d; d >>= 1) acc += __shfl_xor_sync(0xffffffffu, acc, d);
    if ((t & 31) == 0) ws[t >> 5] = acc;
    __syncthreads();
    if (t < 8) {
        int s = ws[t];
#pragma unroll
        for (int d = 4; d; d >>= 1) s += __shfl_xor_sync(0xffu, s, d);
        if (t == 0) sbase = s;
    }
    __syncthreads();
    int vv = orig;
#pragma unroll
    for (int d = 1; d < 32; d <<= 1) {
        int u = __shfl_up_sync(0xffffffffu, vv, d);
        if ((t & 31) >= d) vv += u;
    }
    if ((t & 31) == 31) ws[t >> 5] = vv;
    __syncthreads();
    if (t < 8) {
        int s = ws[t];
#pragma unroll
        for (int d = 1; d < 8; d <<= 1) {
            int u = __shfl_up_sync(0xffu, s, d);
            if (t >= d) s += u;
        }
        ws[t] = s;
    }
    __syncthreads();
    int incl = vv + ((t >= 32) ? ws[(t >> 5) - 1] : 0);
    int excl = incl - orig + sbase;
    if (i < NN) { g_off[i] = excl; g_cnt[i] = 0; }
    if (b == SB - 1 && t == 255) g_off[NN] = NE;
}

// atomic-free scatter: slot = off[dst] + rank (a permutation -> no conflicts)
__global__ void k_scatter(const void* __restrict__ ei) {
    __shared__ int sis64;
    int is64 = detect_is64_block(ei, &sis64);
    int e = blockIdx.x * blockDim.x + threadIdx.x;
    if (e < SB) g_flag[e] = 0;          // reset lookback flags for next replay
    if (e >= NE) return;
    int s, d;
    if (is64) {
        const long long* p = (const long long*)ei;
        s = (int)p[e]; d = (int)p[NE + e];
    } else {
        const int* p = (const int*)ei;
        s = p[e]; d = p[NE + e];
    }
    g_adj[g_off[d] + g_rank[e]] = s;
}

// ---------------- tensor-core GEMM + fused alpha ------------------------------
// 256 threads (8 warps), 128 nodes/block. bf16 mma.sync m16n8k16, fp32 accum.
template <bool FIRST, int H>
__global__ void __launch_bounds__(256) k_gemm(const float* __restrict__ W,
                       const float* __restrict__ ue,
                       const float* __restrict__ ie,
                       const float* __restrict__ a_src,
                       const float* __restrict__ a_dst) {
    __shared__ __nv_bfloat16 sW[64][72];
    __shared__ __nv_bfloat16 sX[128][72];
    int t = threadIdx.x;
    int n0 = blockIdx.x * 128;

    {
        int r = t >> 2, cg = (t & 3) * 16;
#pragma unroll
        for (int i = 0; i < 4; i++) {
            float4 v = *(const float4*)&W[r * 64 + cg + i * 4];
            *(unsigned*)&sW[r][cg + i * 4 + 0] = f2bf2(v.x, v.y);
            *(unsigned*)&sW[r][cg + i * 4 + 2] = f2bf2(v.z, v.w);
        }
    }
    {
        int r = t >> 1, hf = (t & 1) * 32;
        int n = n0 + r;
        if (FIRST) {
            if (n < NN) {
                const float* row = (n < N_USERS) ? ue + (size_t)n * 64
                                                 : ie + (size_t)(n - N_USERS) * 64;
#pragma unroll
                for (int i = 0; i < 8; i++) {
                    float4 v = *(const float4*)&row[hf + i * 4];
                    *(unsigned*)&sX[r][hf + i * 4 + 0] = f2bf2(v.x, v.y);
                    *(unsigned*)&sX[r][hf + i * 4 + 2] = f2bf2(v.z, v.w);
                }
            } else {
#pragma unroll
                for (int i = 0; i < 16; i++) *(unsigned*)&sX[r][hf + i * 2] = 0u;
            }
        } else {
            if (n < NN) {
                const uint4* src = (const uint4*)&g_xb[(size_t)n * 64 + hf];
#pragma unroll
                for (int i = 0; i < 4; i++) *(uint4*)&sX[r][hf + i * 8] = src[i];
            } else {
#pragma unroll
                for (int i = 0; i < 16; i++) *(unsigned*)&sX[r][hf + i * 2] = 0u;
            }
        }
    }
    __syncthreads();

    int wid = t >> 5, lane = t & 31;
    int m0 = wid * 16;
    int grp = lane >> 3, li = lane & 7;

    unsigned afr[4][4];
    {
        int row = m0 + ((grp & 1) ? 8 : 0) + li;
#pragma unroll
        for (int kc = 0; kc < 4; kc++) {
            int col = kc * 16 + ((grp & 2) ? 8 : 0);
            ldsm_x4(afr[kc], smaddr(&sX[row][col]));
        }
    }
    float cfr[8][4];
#pragma unroll
    for (int nt = 0; nt < 8; nt++)
#pragma unroll
        for (int q = 0; q < 4; q++) cfr[nt][q] = 0.f;
    {
        int brow = lane & 15;
#pragma unroll
        for (int nt = 0; nt < 8; nt++) {
#pragma unroll
            for (int kc = 0; kc < 4; kc++) {
                unsigned bfr[2];
                ldsm_x2t(bfr, smaddr(&sW[kc * 16 + brow][nt * 8]));
                mma_bf16(cfr[nt], afr[kc], bfr);
            }
        }
    }
    {
        int r = m0 + (lane >> 2);
        int cbase = (lane & 3) * 2;
#pragma unroll
        for (int nt = 0; nt < 8; nt++) {
            int c = nt * 8 + cbase;
            *(unsigned*)&sX[r][c]     = f2bf2(cfr[nt][0], cfr[nt][1]);
            *(unsigned*)&sX[r + 8][c] = f2bf2(cfr[nt][2], cfr[nt][3]);
        }
    }
    __syncthreads();

    {
        int nb = t >> 1, hf = (t & 1) * 32;
        int n = n0 + nb;
        uint4 v0 = *(const uint4*)&sX[nb][hf];
        uint4 v1 = *(const uint4*)&sX[nb][hf + 8];
        uint4 v2 = *(const uint4*)&sX[nb][hf + 16];
        uint4 v3 = *(const uint4*)&sX[nb][hf + 24];
        unsigned hw[16] = { v0.x, v0.y, v0.z, v0.w, v1.x, v1.y, v1.z, v1.w,
                            v2.x, v2.y, v2.z, v2.w, v3.x, v3.y, v3.z, v3.w };
        if (n < NN) {
            unsigned u[8];
#pragma unroll
            for (int jj = 0; jj < 8; jj++) {
                float2 e0 = bf2f(hw[2 * jj]);
                float2 e1 = bf2f(hw[2 * jj + 1]);
                unsigned short p0 = f2fp8(e0.x * H8_SCALE, e0.y * H8_SCALE);
                unsigned short p1 = f2fp8(e1.x * H8_SCALE, e1.y * H8_SCALE);
                u[jj] = (unsigned)p0 | ((unsigned)p1 << 16);
            }
            uint4* dst = (uint4*)&g_h8[(size_t)n * 64 + hf];
            dst[0] = make_uint4(u[0], u[1], u[2], u[3]);
            dst[1] = make_uint4(u[4], u[5], u[6], u[7]);
        }
        if (H == 4) {
            float ps0 = 0.f, pd0 = 0.f, ps1 = 0.f, pd1 = 0.f;
#pragma unroll
            for (int i = 0; i < 8; i++) {
                float2 hv = bf2f(hw[i]);
                int c = hf + i * 2;
                ps0 += hv.x * a_src[c] + hv.y * a_src[c + 1];
                pd0 += hv.x * a_dst[c] + hv.y * a_dst[c + 1];
            }
#pragma unroll
            for (int i = 8; i < 16; i++) {
                float2 hv = bf2f(hw[i]);
                int c = hf + i * 2;
                ps1 += hv.x * a_src[c] + hv.y * a_src[c + 1];
                pd1 += hv.x * a_dst[c] + hv.y * a_dst[c + 1];
            }
            if (n < NN) {
                int h0 = hf / 16;
                g_as[n * 4 + h0]     = ps0;
                g_ad[n * 4 + h0]     = pd0;
                g_as[n * 4 + h0 + 1] = ps1;
                g_ad[n * 4 + h0 + 1] = pd1;
            }
        } else {
            float ps = 0.f, pd = 0.f;
#pragma unroll
            for (int i = 0; i < 16; i++) {
                float2 hv = bf2f(hw[i]);
                int c = hf + i * 2;
                ps += hv.x * a_src[c] + hv.y * a_src[c + 1];
                pd += hv.x * a_dst[c] + hv.y * a_dst[c + 1];
            }
            ps += __shfl_xor_sync(0xffffffffu, ps, 1);
            pd += __shfl_xor_sync(0xffffffffu, pd, 1);
            if (n < NN && (t & 1) == 0) { g_as[n] = ps; g_ad[n] = pd; }
        }
    }
}

// ---------------- fused aggregation (fp8 payload gathers) --------------------
// 4 nodes/warp, 8 lanes/node, lane owns 8 cols (uint2 = 8 fp8; full row = 64B).
template <int H, int F>
__global__ void k_agg(const float* __restrict__ b) {
    int lane = threadIdx.x & 31;
    int wrp  = threadIdx.x >> 5;
    int quad = lane >> 3;
    int l    = lane & 7;
    int n    = blockIdx.x * 32 + wrp * 4 + quad;
    if (n >= NN) return;
    int c0   = l * 8;
    int head = c0 / F;

    float ad_d = __ldg(&g_ad[(size_t)n * H + head]);
    float den  = __expf(lrelu(__ldg(&g_as[(size_t)n * H + head]) + ad_d));
    const uint2* h8 = (const uint2*)g_h8;   // row = 8 uint2 (64 fp8)
    uint2 hs = h8[(size_t)n * 8 + l];
    float2 f0, f1, f2, f3;
    fp8x4_f32(hs.x, f0, f1);
    fp8x4_f32(hs.y, f2, f3);
    float a0 = den * f0.x, a1 = den * f0.y, a2 = den * f1.x, a3 = den * f1.y;
    float a4 = den * f2.x, a5 = den * f2.y, a6 = den * f3.x, a7 = den * f3.y;

    int beg = g_off[n], end = g_off[n + 1];
    int j = beg;
    for (; j + 4 <= end; j += 4) {
        int s[4]; float w[4]; uint2 p[4];
#pragma unroll
        for (int q = 0; q < 4; q++) s[q] = __ldg(&g_adj[j + q]);
#pragma unroll
        for (int q = 0; q < 4; q++) p[q] = h8[(size_t)s[q] * 8 + l];
#pragma unroll
        for (int q = 0; q < 4; q++)
            w[q] = __expf(lrelu(__ldg(&g_as[(size_t)s[q] * H + head]) + ad_d));
#pragma unroll
        for (int q = 0; q < 4; q++) {
            float2 q0, q1, q2, q3;
            fp8x4_f32(p[q].x, q0, q1);
            fp8x4_f32(p[q].y, q2, q3);
            den += w[q];
            a0 += w[q] * q0.x; a1 += w[q] * q0.y;
            a2 += w[q] * q1.x; a3 += w[q] * q1.y;
            a4 += w[q] * q2.x; a5 += w[q] * q2.y;
            a6 += w[q] * q3.x; a7 += w[q] * q3.y;
        }
    }
    for (; j < end; j++) {
        int s = __ldg(&g_adj[j]);
        uint2 p = h8[(size_t)s * 8 + l];
        float w = __expf(lrelu(__ldg(&g_as[(size_t)s * H + head]) + ad_d));
        float2 q0, q1, q2, q3;
        fp8x4_f32(p.x, q0, q1);
        fp8x4_f32(p.y, q2, q3);
        den += w;
        a0 += w * q0.x; a1 += w * q0.y; a2 += w * q1.x; a3 += w * q1.y;
        a4 += w * q2.x; a5 += w * q2.y; a6 += w * q3.x; a7 += w * q3.y;
    }
    float inv = 1.f / (den * H8_SCALE);   // undo payload scale once
    uint4 o;
    o.x = f2bf2(eluf(a0 * inv + b[c0 + 0]), eluf(a1 * inv + b[c0 + 1]));
    o.y = f2bf2(eluf(a2 * inv + b[c0 + 2]), eluf(a3 * inv + b[c0 + 3]));
    o.z = f2bf2(eluf(a4 * inv + b[c0 + 4]), eluf(a5 * inv + b[c0 + 5]));
    o.w = f2bf2(eluf(a6 * inv + b[c0 + 6]), eluf(a7 * inv + b[c0 + 7]));
    *(uint4*)&g_xb[(size_t)n * 64 + c0] = o;
}

// ---------------- final scoring (bf16 features) -------------------------------
__global__ void k_score(const void* __restrict__ bu_, const void* __restrict__ bi_,
                        float* __restrict__ out) {
    __shared__ int sis64;
    int is64 = detect_is64_block(bu_, &sis64);
    int gid = blockIdx.x * blockDim.x + threadIdx.x;
    if (gid >= NB * 8) return;
    int p = gid >> 3, l = gid & 7;
    int u, it;
    if (is64) {
        u  = (int)((const long long*)bu_)[p];
        it = (int)((const long long*)bi_)[p];
    } else {
        u  = ((const int*)bu_)[p];
        it = ((const int*)bi_)[p];
    }
    const uint4* xb = (const uint4*)g_xb;
    uint4 av = xb[(size_t)u * 8 + l];
    uint4 bv = xb[((size_t)it + N_USERS) * 8 + l];
    float acc;
    {
        float2 a01 = bf2f(av.x), b01 = bf2f(bv.x);
        float2 a23 = bf2f(av.y), b23 = bf2f(bv.y);
        float2 a45 = bf2f(av.z), b45 = bf2f(bv.z);
        float2 a67 = bf2f(av.w), b67 = bf2f(bv.w);
        acc = a01.x * b01.x + a01.y * b01.y + a23.x * b23.x + a23.y * b23.y
            + a45.x * b45.x + a45.y * b45.y + a67.x * b67.x + a67.y * b67.y;
    }
    acc += __shfl_xor_sync(0xffffffffu, acc, 1);
    acc += __shfl_xor_sync(0xffffffffu, acc, 2);
    acc += __shfl_xor_sync(0xffffffffu, acc, 4);
    if (l == 0) out[p] = 1.f / (1.f + expf(-acc));
}

// ---------------- host launcher ----------------------------------------------
extern "C" void kernel_launch(void* const* d_in, const int* in_sizes, int n_in,
                              void* d_out, int out_size) {
    const void *edge = nullptr, *bu = nullptr, *bi = nullptr;
    const float *ue = nullptr, *ie = nullptr, *W1 = nullptr, *W2 = nullptr;
    const float* v64[6] = {nullptr, nullptr, nullptr, nullptr, nullptr, nullptr};
    int c64 = 0;
    for (int i = 0; i < n_in; i++) {
        int sz = in_sizes[i];
        if      (sz == 2 * NE)        edge = d_in[i];
        else if (sz == NB)            { if (!bu) bu = d_in[i]; else bi = d_in[i]; }
        else if (sz == N_USERS * DD)  ue = (const float*)d_in[i];
        else if (sz == N_ITEMS * DD)  ie = (const float*)d_in[i];
        else if (sz == DD * DD)       { if (!W1) W1 = (const float*)d_in[i];
                                        else     W2 = (const float*)d_in[i]; }
        else if (sz == 64 && c64 < 6) v64[c64++] = (const float*)d_in[i];
    }
    const float *as1 = v64[0], *ad1 = v64[1], *b1 = v64[2];
    const float *as2 = v64[3], *ad2 = v64[4], *b2 = v64[5];

    const int TB = 256;
    const int EB = (NE + TB - 1) / TB;
    const int GB = (NN + 127) / 128;

    static cudaStream_t s2 = nullptr;
    static cudaEvent_t  evA = nullptr, evB = nullptr;
    static int init_done = 0;
    if (!init_done) {
        if (cudaStreamCreateWithFlags(&s2, cudaStreamNonBlocking) != cudaSuccess) s2 = nullptr;
        if (cudaEventCreateWithFlags(&evA, cudaEventDisableTiming) != cudaSuccess) evA = nullptr;
        if (cudaEventCreateWithFlags(&evB, cudaEventDisableTiming) != cudaSuccess) evB = nullptr;
        init_done = 1;
    }

    bool fork = false;
    if (s2 && evA && evB) {
        if (cudaEventRecord(evA, 0) == cudaSuccess &&
            cudaStreamWaitEvent(s2, evA, 0) == cudaSuccess)
            fork = true;
    }

    if (fork) {
        k_gemm<true, 4><<<GB, 256, 0, s2>>>(W1, ue, ie, as1, ad1);
        if (cudaEventRecord(evB, s2) != cudaSuccess) fork = false;
    }

    // CSR build chain (stream 0)
    k_count  <<<EB, TB>>>(edge);
    k_scan   <<<SB, 256>>>();
    k_scatter<<<EB, TB>>>(edge);

    if (fork) {
        cudaStreamWaitEvent(0, evB, 0);
    } else {
        k_gemm<true, 4><<<GB, 256>>>(W1, ue, ie, as1, ad1);
    }

    k_agg <4, 16>   <<<(NN + 31) / 32, TB>>>(b1);
    k_gemm<false, 1><<<GB, 256>>>(W2, nullptr, nullptr, as2, ad2);
    k_agg <1, 64>   <<<(NN + 31) / 32, TB>>>(b2);
    k_score<<<(NB * 8 + TB - 1) / TB, TB>>>(bu, bi, (float*)d_out);
}